// round 5
// baseline (speedup 1.0000x reference)
#include <cuda_runtime.h>
#include <cuda_fp16.h>
#include <cstdint>

#define NN 100000
#define NE 1600000
#define FF 64
#define F2 (FF/2)   // float2 lanes
#define H2 (FF/2)   // half2 lanes (32 per row)

#define TH0 0.6f
#define TH1 (-0.4f)
#define TH2 0.3f
#define TH3 (-0.2f)
#define TH4 0.1f

// ---- scratch (static device globals; no runtime allocation) ----
__device__ __half g_f16_0[NN * FF];
__device__ __half g_f16_1[NN * FF];
__device__ __half g_f16_2[NN * FF];
__device__ __half g_f16_3[NN * FF];
__device__ __half g_f16_4[NN * FF];
__device__ int    g_deg[NN];
__device__ int    g_off[NN];
__device__ int    g_cursor[NN];
__device__ float  g_dis[NN];
__device__ int2   g_edgeSorted[NE];   // .x = src*32 (half2 row base), .y = bits(dis[src])
__device__ int    g_blockSums[256];

// ---------------- preprocessing ----------------

__global__ void k_zero(int n) {
    int i = blockIdx.x * blockDim.x + threadIdx.x;
    if (i < n) { g_deg[i] = 0; g_cursor[i] = 0; }
}

// 4 edges per thread via int4
__global__ void k_hist(const int* __restrict__ edge, int e4) {
    int i = blockIdx.x * blockDim.x + threadIdx.x;
    if (i < e4) {
        int4 d = ((const int4*)(edge + NE))[i];
        atomicAdd(&g_deg[d.x], 1);
        atomicAdd(&g_deg[d.y], 1);
        atomicAdd(&g_deg[d.z], 1);
        atomicAdd(&g_deg[d.w], 1);
    }
}

__global__ void k_dis(int n) {
    int i = blockIdx.x * blockDim.x + threadIdx.x;
    if (i < n) {
        int d = g_deg[i];
        g_dis[i] = rsqrtf((float)(d < 1 ? 1 : d));
    }
}

__global__ void k_scan1(int n) {
    __shared__ int warpSums[32];
    int i = blockIdx.x * 1024 + threadIdx.x;
    int v = (i < n) ? g_deg[i] : 0;
    int lane = threadIdx.x & 31, wid = threadIdx.x >> 5;
    int x = v;
    #pragma unroll
    for (int o = 1; o < 32; o <<= 1) {
        int t = __shfl_up_sync(0xffffffffu, x, o);
        if (lane >= o) x += t;
    }
    if (lane == 31) warpSums[wid] = x;
    __syncthreads();
    if (wid == 0) {
        int s = warpSums[lane];
        #pragma unroll
        for (int o = 1; o < 32; o <<= 1) {
            int t = __shfl_up_sync(0xffffffffu, s, o);
            if (lane >= o) s += t;
        }
        warpSums[lane] = s;
    }
    __syncthreads();
    int prefix = (wid > 0 ? warpSums[wid - 1] : 0) + (x - v);
    if (i < n) g_off[i] = prefix;
    if (threadIdx.x == 1023) g_blockSums[blockIdx.x] = warpSums[31];
}

__global__ void k_scan2(int nb) {
    if (threadIdx.x == 0 && blockIdx.x == 0) {
        int acc = 0;
        for (int b = 0; b < nb; b++) { int t = g_blockSums[b]; g_blockSums[b] = acc; acc += t; }
    }
}

__global__ void k_scan3(int n) {
    int i = blockIdx.x * 1024 + threadIdx.x;
    if (i < n) g_off[i] += g_blockSums[blockIdx.x];
}

// 4 edges per thread via int4 on both src and dst rows
__global__ void k_scatter(const int* __restrict__ edge, int e4) {
    int i = blockIdx.x * blockDim.x + threadIdx.x;
    if (i < e4) {
        int4 s = ((const int4*)edge)[i];
        int4 d = ((const int4*)(edge + NE))[i];
        float w0 = g_dis[s.x], w1 = g_dis[s.y], w2 = g_dis[s.z], w3 = g_dis[s.w];
        int p0 = g_off[d.x] + atomicAdd(&g_cursor[d.x], 1);
        int p1 = g_off[d.y] + atomicAdd(&g_cursor[d.y], 1);
        int p2 = g_off[d.z] + atomicAdd(&g_cursor[d.z], 1);
        int p3 = g_off[d.w] + atomicAdd(&g_cursor[d.w], 1);
        g_edgeSorted[p0] = make_int2(s.x * H2, __float_as_int(w0));
        g_edgeSorted[p1] = make_int2(s.y * H2, __float_as_int(w1));
        g_edgeSorted[p2] = make_int2(s.z * H2, __float_as_int(w2));
        g_edgeSorted[p3] = make_int2(s.w * H2, __float_as_int(w3));
    }
}

// x fp32 -> f0 fp16
__global__ void k_tohalf(const float* __restrict__ x, int n2) {
    int i = blockIdx.x * blockDim.x + threadIdx.x;
    if (i < n2) {
        float2 v = ((const float2*)x)[i];
        ((__half2*)g_f16_0)[i] = __float22half2_rn(v);
    }
}

// ---------------- propagation step: warp per node, half2 per lane ----------------
// Unroll x4 with front-batched independent loads to raise MLP: 4 edge-record
// LDGs issue together, then 4 gather LDGs, so the dependent chain is 2-deep
// per 4 edges instead of per 1 edge.

template <int STEP>
__global__ void __launch_bounds__(256) k_step(int n) {
    int node = (blockIdx.x * blockDim.x + threadIdx.x) >> 5;
    int lane = threadIdx.x & 31;
    if (node >= n) return;

    const __half2* __restrict__ fp =
        (STEP == 1) ? (const __half2*)g_f16_0 :
        (STEP == 2) ? (const __half2*)g_f16_1 :
        (STEP == 3) ? (const __half2*)g_f16_2 :
                      (const __half2*)g_f16_3;
    __half2* __restrict__ fn =
        (STEP == 1) ? (__half2*)g_f16_1 :
        (STEP == 2) ? (__half2*)g_f16_2 :
        (STEP == 3) ? (__half2*)g_f16_3 :
                      (__half2*)g_f16_4;

    int beg = g_off[node];
    int cnt = g_deg[node];

    const int2* __restrict__ es = (const int2*)g_edgeSorted;

    float2 acc = make_float2(0.f, 0.f);
    int e = 0;
    for (; e + 3 < cnt; e += 4) {
        int2 r0 = __ldg(&es[beg + e]);
        int2 r1 = __ldg(&es[beg + e + 1]);
        int2 r2 = __ldg(&es[beg + e + 2]);
        int2 r3 = __ldg(&es[beg + e + 3]);
        __half2 g0 = __ldg(&fp[r0.x + lane]);
        __half2 g1 = __ldg(&fp[r1.x + lane]);
        __half2 g2 = __ldg(&fp[r2.x + lane]);
        __half2 g3 = __ldg(&fp[r3.x + lane]);
        float2 v0 = __half22float2(g0);
        float2 v1 = __half22float2(g1);
        float2 v2 = __half22float2(g2);
        float2 v3 = __half22float2(g3);
        float w0 = __int_as_float(r0.y);
        float w1 = __int_as_float(r1.y);
        float w2 = __int_as_float(r2.y);
        float w3 = __int_as_float(r3.y);
        acc.x += w0 * v0.x + w1 * v1.x + w2 * v2.x + w3 * v3.x;
        acc.y += w0 * v0.y + w1 * v1.y + w2 * v2.y + w3 * v3.y;
    }
    for (; e < cnt; e++) {
        int2 r0 = __ldg(&es[beg + e]);
        float2 v0 = __half22float2(__ldg(&fp[r0.x + lane]));
        float w0 = __int_as_float(r0.y);
        acc.x += w0 * v0.x;
        acc.y += w0 * v0.y;
    }

    float din = g_dis[node];
    int idx = node * H2 + lane;
    float2 prev = __half22float2(__ldg(&fp[idx]));
    float2 out;
    out.x = prev.x - din * acc.x;
    out.y = prev.y - din * acc.y;
    fn[idx] = __float22half2_rn(out);
}

// ---------------- final combine: h = th0*x + sum th_k * f_k ----------------

__global__ void k_combine(const float* __restrict__ x, float* __restrict__ h, int n2) {
    int i = blockIdx.x * blockDim.x + threadIdx.x;
    if (i < n2) {
        float2 xv = ((const float2*)x)[i];
        float2 f1 = __half22float2(((const __half2*)g_f16_1)[i]);
        float2 f2 = __half22float2(((const __half2*)g_f16_2)[i]);
        float2 f3 = __half22float2(((const __half2*)g_f16_3)[i]);
        float2 f4 = __half22float2(((const __half2*)g_f16_4)[i]);
        float2 o;
        o.x = TH0 * xv.x + TH1 * f1.x + TH2 * f2.x + TH3 * f3.x + TH4 * f4.x;
        o.y = TH0 * xv.y + TH1 * f1.y + TH2 * f2.y + TH3 * f3.y + TH4 * f4.y;
        ((float2*)h)[i] = o;
    }
}

// ---------------- launcher ----------------

extern "C" void kernel_launch(void* const* d_in, const int* in_sizes, int n_in,
                              void* d_out, int out_size)
{
    const float* x    = (const float*)d_in[0];   // [N, 64] fp32
    const int*   edge = (const int*)d_in[1];     // [2, E] int32

    const int n = NN;
    const int e4 = NE / 4;                   // 400k int4 records
    const int n2 = NN * F2;
    const int NB_SCAN = (n + 1023) / 1024;

    float* h = (float*)d_out;

    k_zero<<<(n + 255) / 256, 256>>>(n);
    k_hist<<<(e4 + 255) / 256, 256>>>(edge, e4);
    k_dis<<<(n + 255) / 256, 256>>>(n);
    k_scan1<<<NB_SCAN, 1024>>>(n);
    k_scan2<<<1, 32>>>(NB_SCAN);
    k_scan3<<<NB_SCAN, 1024>>>(n);
    k_scatter<<<(e4 + 255) / 256, 256>>>(edge, e4);
    k_tohalf<<<(n2 + 255) / 256, 256>>>(x, n2);

    const int TPB = 256;
    const int NBLK = (n * 32 + TPB - 1) / TPB;   // warp per node

    k_step<1><<<NBLK, TPB>>>(n);
    k_step<2><<<NBLK, TPB>>>(n);
    k_step<3><<<NBLK, TPB>>>(n);
    k_step<4><<<NBLK, TPB>>>(n);

    k_combine<<<(n2 + 255) / 256, 256>>>(x, h, n2);
}

// round 6
// speedup vs baseline: 1.1129x; 1.1129x over previous
#include <cuda_runtime.h>
#include <cuda_fp16.h>
#include <cstdint>

#define NN 100000
#define NE 1600000
#define FF 64
#define F2 (FF/2)   // float2 lanes per row
#define H8 16       // 8-byte slots per row (64 halves = 128B = 16 x 8B)

#define TH0 0.6f
#define TH1 (-0.4f)
#define TH2 0.3f
#define TH3 (-0.2f)
#define TH4 0.1f

// ---- scratch (static device globals; no runtime allocation) ----
__device__ __half g_f16_0[NN * FF];
__device__ __half g_f16_1[NN * FF];
__device__ __half g_f16_2[NN * FF];
__device__ __half g_f16_3[NN * FF];
__device__ __half g_f16_4[NN * FF];
__device__ int    g_deg[NN];
__device__ int    g_off[NN];
__device__ int    g_cursor[NN];
__device__ float  g_dis[NN];
__device__ int2   g_edgeSorted[NE];   // .x = src*16 (8B-slot row base), .y = bits(dis[src])
__device__ int    g_blockSums[256];

// ---------------- preprocessing ----------------

__global__ void k_zero(int n) {
    int i = blockIdx.x * blockDim.x + threadIdx.x;
    if (i < n) { g_deg[i] = 0; g_cursor[i] = 0; }
}

__global__ void k_hist(const int* __restrict__ edge, int e4) {
    int i = blockIdx.x * blockDim.x + threadIdx.x;
    if (i < e4) {
        int4 d = ((const int4*)(edge + NE))[i];
        atomicAdd(&g_deg[d.x], 1);
        atomicAdd(&g_deg[d.y], 1);
        atomicAdd(&g_deg[d.z], 1);
        atomicAdd(&g_deg[d.w], 1);
    }
}

__global__ void k_dis(int n) {
    int i = blockIdx.x * blockDim.x + threadIdx.x;
    if (i < n) {
        int d = g_deg[i];
        g_dis[i] = rsqrtf((float)(d < 1 ? 1 : d));
    }
}

__global__ void k_scan1(int n) {
    __shared__ int warpSums[32];
    int i = blockIdx.x * 1024 + threadIdx.x;
    int v = (i < n) ? g_deg[i] : 0;
    int lane = threadIdx.x & 31, wid = threadIdx.x >> 5;
    int x = v;
    #pragma unroll
    for (int o = 1; o < 32; o <<= 1) {
        int t = __shfl_up_sync(0xffffffffu, x, o);
        if (lane >= o) x += t;
    }
    if (lane == 31) warpSums[wid] = x;
    __syncthreads();
    if (wid == 0) {
        int s = warpSums[lane];
        #pragma unroll
        for (int o = 1; o < 32; o <<= 1) {
            int t = __shfl_up_sync(0xffffffffu, s, o);
            if (lane >= o) s += t;
        }
        warpSums[lane] = s;
    }
    __syncthreads();
    int prefix = (wid > 0 ? warpSums[wid - 1] : 0) + (x - v);
    if (i < n) g_off[i] = prefix;
    if (threadIdx.x == 1023) g_blockSums[blockIdx.x] = warpSums[31];
}

__global__ void k_scan2(int nb) {
    if (threadIdx.x == 0 && blockIdx.x == 0) {
        int acc = 0;
        for (int b = 0; b < nb; b++) { int t = g_blockSums[b]; g_blockSums[b] = acc; acc += t; }
    }
}

__global__ void k_scan3(int n) {
    int i = blockIdx.x * 1024 + threadIdx.x;
    if (i < n) g_off[i] += g_blockSums[blockIdx.x];
}

__global__ void k_scatter(const int* __restrict__ edge, int e4) {
    int i = blockIdx.x * blockDim.x + threadIdx.x;
    if (i < e4) {
        int4 s = ((const int4*)edge)[i];
        int4 d = ((const int4*)(edge + NE))[i];
        float w0 = g_dis[s.x], w1 = g_dis[s.y], w2 = g_dis[s.z], w3 = g_dis[s.w];
        int p0 = g_off[d.x] + atomicAdd(&g_cursor[d.x], 1);
        int p1 = g_off[d.y] + atomicAdd(&g_cursor[d.y], 1);
        int p2 = g_off[d.z] + atomicAdd(&g_cursor[d.z], 1);
        int p3 = g_off[d.w] + atomicAdd(&g_cursor[d.w], 1);
        g_edgeSorted[p0] = make_int2(s.x * H8, __float_as_int(w0));
        g_edgeSorted[p1] = make_int2(s.y * H8, __float_as_int(w1));
        g_edgeSorted[p2] = make_int2(s.z * H8, __float_as_int(w2));
        g_edgeSorted[p3] = make_int2(s.w * H8, __float_as_int(w3));
    }
}

// x fp32 -> f0 fp16
__global__ void k_tohalf(const float* __restrict__ x, int n2) {
    int i = blockIdx.x * blockDim.x + threadIdx.x;
    if (i < n2) {
        float2 v = ((const float2*)x)[i];
        ((__half2*)g_f16_0)[i] = __float22half2_rn(v);
    }
}

// ---------------- propagation step ----------------
// Warp per node. Each lane owns an 8B slice (4 halves) of the 128B row; the
// two half-warps process two edges per gather LDG: lanes 0-15 -> edge e,
// lanes 16-31 -> edge e+1. One LDG per edge total (record + row amortized to
// two LDGs per two edges). Half-warp partials folded with shfl_xor(16).

template <int STEP>
__global__ void __launch_bounds__(256) k_step(int n) {
    int node = (blockIdx.x * blockDim.x + threadIdx.x) >> 5;
    int lane = threadIdx.x & 31;
    if (node >= n) return;
    int half = lane >> 4;     // 0 or 1
    int sub  = lane & 15;     // 8B slot within row

    const int2* __restrict__ f8 =
        (STEP == 1) ? (const int2*)g_f16_0 :
        (STEP == 2) ? (const int2*)g_f16_1 :
        (STEP == 3) ? (const int2*)g_f16_2 :
                      (const int2*)g_f16_3;
    int2* __restrict__ fo8 =
        (STEP == 1) ? (int2*)g_f16_1 :
        (STEP == 2) ? (int2*)g_f16_2 :
        (STEP == 3) ? (int2*)g_f16_3 :
                      (int2*)g_f16_4;

    int beg = g_off[node];
    int cnt = g_deg[node];
    const int2* __restrict__ es = (const int2*)g_edgeSorted;

    float ax = 0.f, ay = 0.f, az = 0.f, aw = 0.f;
    int e = 0;
    for (; e + 3 < cnt; e += 4) {
        int2 r0 = __ldg(&es[beg + e + half]);          // pair (e, e+1)
        int2 r1 = __ldg(&es[beg + e + 2 + half]);      // pair (e+2, e+3)
        int2 v0 = __ldg(&f8[r0.x + sub]);
        int2 v1 = __ldg(&f8[r1.x + sub]);
        float w0 = __int_as_float(r0.y);
        float w1 = __int_as_float(r1.y);
        float2 a0 = __half22float2(*reinterpret_cast<const __half2*>(&v0.x));
        float2 b0 = __half22float2(*reinterpret_cast<const __half2*>(&v0.y));
        float2 a1 = __half22float2(*reinterpret_cast<const __half2*>(&v1.x));
        float2 b1 = __half22float2(*reinterpret_cast<const __half2*>(&v1.y));
        ax += w0 * a0.x + w1 * a1.x;
        ay += w0 * a0.y + w1 * a1.y;
        az += w0 * b0.x + w1 * b1.x;
        aw += w0 * b0.y + w1 * b1.y;
    }
    for (; e < cnt; e += 2) {
        bool valid = (e + half) < cnt;
        int2 r = valid ? __ldg(&es[beg + e + half]) : make_int2(0, 0);
        int2 v = __ldg(&f8[r.x + sub]);                // row 0 if invalid, w=0
        float w = __int_as_float(r.y);
        float2 a = __half22float2(*reinterpret_cast<const __half2*>(&v.x));
        float2 b = __half22float2(*reinterpret_cast<const __half2*>(&v.y));
        ax += w * a.x;
        ay += w * a.y;
        az += w * b.x;
        aw += w * b.y;
    }

    // fold the two half-warp partials
    ax += __shfl_xor_sync(0xffffffffu, ax, 16);
    ay += __shfl_xor_sync(0xffffffffu, ay, 16);
    az += __shfl_xor_sync(0xffffffffu, az, 16);
    aw += __shfl_xor_sync(0xffffffffu, aw, 16);

    float din = g_dis[node];
    int ridx = node * H8 + sub;
    if (half == 0) {
        int2 pv = __ldg(&f8[ridx]);
        float2 p0 = __half22float2(*reinterpret_cast<const __half2*>(&pv.x));
        float2 p1 = __half22float2(*reinterpret_cast<const __half2*>(&pv.y));
        float2 o0, o1;
        o0.x = p0.x - din * ax;
        o0.y = p0.y - din * ay;
        o1.x = p1.x - din * az;
        o1.y = p1.y - din * aw;
        __half2 s0 = __float22half2_rn(o0);
        __half2 s1 = __float22half2_rn(o1);
        int2 st;
        st.x = *reinterpret_cast<const int*>(&s0);
        st.y = *reinterpret_cast<const int*>(&s1);
        fo8[ridx] = st;
    }
}

// ---------------- final combine: h = th0*x + sum th_k * f_k ----------------

__global__ void k_combine(const float* __restrict__ x, float* __restrict__ h, int n2) {
    int i = blockIdx.x * blockDim.x + threadIdx.x;
    if (i < n2) {
        float2 xv = ((const float2*)x)[i];
        float2 f1 = __half22float2(((const __half2*)g_f16_1)[i]);
        float2 f2 = __half22float2(((const __half2*)g_f16_2)[i]);
        float2 f3 = __half22float2(((const __half2*)g_f16_3)[i]);
        float2 f4 = __half22float2(((const __half2*)g_f16_4)[i]);
        float2 o;
        o.x = TH0 * xv.x + TH1 * f1.x + TH2 * f2.x + TH3 * f3.x + TH4 * f4.x;
        o.y = TH0 * xv.y + TH1 * f1.y + TH2 * f2.y + TH3 * f3.y + TH4 * f4.y;
        ((float2*)h)[i] = o;
    }
}

// ---------------- launcher ----------------

extern "C" void kernel_launch(void* const* d_in, const int* in_sizes, int n_in,
                              void* d_out, int out_size)
{
    const float* x    = (const float*)d_in[0];   // [N, 64] fp32
    const int*   edge = (const int*)d_in[1];     // [2, E] int32

    const int n = NN;
    const int e4 = NE / 4;
    const int n2 = NN * F2;
    const int NB_SCAN = (n + 1023) / 1024;

    float* h = (float*)d_out;

    k_zero<<<(n + 255) / 256, 256>>>(n);
    k_hist<<<(e4 + 255) / 256, 256>>>(edge, e4);
    k_dis<<<(n + 255) / 256, 256>>>(n);
    k_scan1<<<NB_SCAN, 1024>>>(n);
    k_scan2<<<1, 32>>>(NB_SCAN);
    k_scan3<<<NB_SCAN, 1024>>>(n);
    k_scatter<<<(e4 + 255) / 256, 256>>>(edge, e4);
    k_tohalf<<<(n2 + 255) / 256, 256>>>(x, n2);

    const int TPB = 256;
    const int NBLK = (n * 32 + TPB - 1) / TPB;   // warp per node

    k_step<1><<<NBLK, TPB>>>(n);
    k_step<2><<<NBLK, TPB>>>(n);
    k_step<3><<<NBLK, TPB>>>(n);
    k_step<4><<<NBLK, TPB>>>(n);

    k_combine<<<(n2 + 255) / 256, 256>>>(x, h, n2);
}

// round 8
// speedup vs baseline: 1.1833x; 1.0632x over previous
#include <cuda_runtime.h>
#include <cuda_fp16.h>
#include <cstdint>

#define NN 100000
#define NE 1600000
#define FF 64
#define F2 (FF/2)   // float2 lanes per row
#define S16 8       // 16-byte slots per row (64 halves = 128B = 8 x 16B)

#define TH0 0.6f
#define TH1 (-0.4f)
#define TH2 0.3f
#define TH3 (-0.2f)
#define TH4 0.1f

// ---- scratch (static device globals; no runtime allocation) ----
__device__ __half g_f16_0[NN * FF];
__device__ __half g_f16_1[NN * FF];
__device__ __half g_f16_2[NN * FF];
__device__ __half g_f16_3[NN * FF];
__device__ int    g_deg[NN];
__device__ int    g_off[NN];
__device__ int    g_cursor[NN];
__device__ float  g_dis[NN];
__device__ int2   g_edgeSorted[NE];   // .x = src*8 (16B-slot row base), .y = bits(dis[src])
__device__ int    g_blockSums[256];

// ---------------- preprocessing ----------------

// zero deg/cursor AND convert x -> fp16 in one launch (grid over n2)
__global__ void k_zero_tohalf(const float* __restrict__ x, int n, int n2) {
    int i = blockIdx.x * blockDim.x + threadIdx.x;
    if (i < n2) {
        float2 v = ((const float2*)x)[i];
        ((__half2*)g_f16_0)[i] = __float22half2_rn(v);
    }
    if (i < n) { g_deg[i] = 0; g_cursor[i] = 0; }
}

__global__ void k_hist(const int* __restrict__ edge, int e4) {
    int i = blockIdx.x * blockDim.x + threadIdx.x;
    if (i < e4) {
        int4 d = ((const int4*)(edge + NE))[i];
        atomicAdd(&g_deg[d.x], 1);
        atomicAdd(&g_deg[d.y], 1);
        atomicAdd(&g_deg[d.z], 1);
        atomicAdd(&g_deg[d.w], 1);
    }
}

// scan phase 1, also computes g_dis from deg (deg already read here)
__global__ void k_scan1(int n) {
    __shared__ int warpSums[32];
    int i = blockIdx.x * 1024 + threadIdx.x;
    int v = (i < n) ? g_deg[i] : 0;
    if (i < n) g_dis[i] = rsqrtf((float)(v < 1 ? 1 : v));
    int lane = threadIdx.x & 31, wid = threadIdx.x >> 5;
    int x = v;
    #pragma unroll
    for (int o = 1; o < 32; o <<= 1) {
        int t = __shfl_up_sync(0xffffffffu, x, o);
        if (lane >= o) x += t;
    }
    if (lane == 31) warpSums[wid] = x;
    __syncthreads();
    if (wid == 0) {
        int s = warpSums[lane];
        #pragma unroll
        for (int o = 1; o < 32; o <<= 1) {
            int t = __shfl_up_sync(0xffffffffu, s, o);
            if (lane >= o) s += t;
        }
        warpSums[lane] = s;
    }
    __syncthreads();
    int prefix = (wid > 0 ? warpSums[wid - 1] : 0) + (x - v);
    if (i < n) g_off[i] = prefix;
    if (threadIdx.x == 1023) g_blockSums[blockIdx.x] = warpSums[31];
}

__global__ void k_scan2(int nb) {
    if (threadIdx.x == 0 && blockIdx.x == 0) {
        int acc = 0;
        for (int b = 0; b < nb; b++) { int t = g_blockSums[b]; g_blockSums[b] = acc; acc += t; }
    }
}

__global__ void k_scan3(int n) {
    int i = blockIdx.x * 1024 + threadIdx.x;
    if (i < n) g_off[i] += g_blockSums[blockIdx.x];
}

__global__ void k_scatter(const int* __restrict__ edge, int e4) {
    int i = blockIdx.x * blockDim.x + threadIdx.x;
    if (i < e4) {
        int4 s = ((const int4*)edge)[i];
        int4 d = ((const int4*)(edge + NE))[i];
        float w0 = g_dis[s.x], w1 = g_dis[s.y], w2 = g_dis[s.z], w3 = g_dis[s.w];
        int p0 = g_off[d.x] + atomicAdd(&g_cursor[d.x], 1);
        int p1 = g_off[d.y] + atomicAdd(&g_cursor[d.y], 1);
        int p2 = g_off[d.z] + atomicAdd(&g_cursor[d.z], 1);
        int p3 = g_off[d.w] + atomicAdd(&g_cursor[d.w], 1);
        g_edgeSorted[p0] = make_int2(s.x * S16, __float_as_int(w0));
        g_edgeSorted[p1] = make_int2(s.y * S16, __float_as_int(w1));
        g_edgeSorted[p2] = make_int2(s.z * S16, __float_as_int(w2));
        g_edgeSorted[p3] = make_int2(s.w * S16, __float_as_int(w3));
    }
}

// ---------------- propagation step ----------------
// Warp per node. Each lane owns a 16B slice (8 halves) of the 128B row; the
// four quarter-warps process 4 edges per gather LDG.128 (512B/warp-instr).
// Edge records: one LDG.64 covers 4 records (quarters read distinct records).
// Quarter partials folded with shfl_xor(8) + shfl_xor(16).
// FINAL=true fuses the polynomial combine: writes h = th0*x + ... directly.

template <int STEP, bool FINAL>
__global__ void __launch_bounds__(256) k_step(const float* __restrict__ x,
                                              float* __restrict__ hOut, int n) {
    int node = (blockIdx.x * blockDim.x + threadIdx.x) >> 5;
    int lane = threadIdx.x & 31;
    if (node >= n) return;
    int q   = lane >> 3;     // quarter 0..3
    int sub = lane & 7;      // 16B slot within row

    const int4* __restrict__ fp =
        (STEP == 1) ? (const int4*)g_f16_0 :
        (STEP == 2) ? (const int4*)g_f16_1 :
        (STEP == 3) ? (const int4*)g_f16_2 :
                      (const int4*)g_f16_3;

    int beg = g_off[node];
    int cnt = g_deg[node];
    const int2* __restrict__ es = (const int2*)g_edgeSorted;

    float a0 = 0.f, a1 = 0.f, a2 = 0.f, a3 = 0.f;
    float a4 = 0.f, a5 = 0.f, a6 = 0.f, a7 = 0.f;

    int e = 0;
    for (; e + 7 < cnt; e += 8) {
        int2 r0 = __ldg(&es[beg + e + q]);
        int2 r1 = __ldg(&es[beg + e + 4 + q]);
        int4 v0 = __ldg(&fp[r0.x + sub]);
        int4 v1 = __ldg(&fp[r1.x + sub]);
        float w0 = __int_as_float(r0.y);
        float w1 = __int_as_float(r1.y);
        float2 c;
        c = __half22float2(*reinterpret_cast<const __half2*>(&v0.x)); a0 += w0 * c.x; a1 += w0 * c.y;
        c = __half22float2(*reinterpret_cast<const __half2*>(&v0.y)); a2 += w0 * c.x; a3 += w0 * c.y;
        c = __half22float2(*reinterpret_cast<const __half2*>(&v0.z)); a4 += w0 * c.x; a5 += w0 * c.y;
        c = __half22float2(*reinterpret_cast<const __half2*>(&v0.w)); a6 += w0 * c.x; a7 += w0 * c.y;
        c = __half22float2(*reinterpret_cast<const __half2*>(&v1.x)); a0 += w1 * c.x; a1 += w1 * c.y;
        c = __half22float2(*reinterpret_cast<const __half2*>(&v1.y)); a2 += w1 * c.x; a3 += w1 * c.y;
        c = __half22float2(*reinterpret_cast<const __half2*>(&v1.z)); a4 += w1 * c.x; a5 += w1 * c.y;
        c = __half22float2(*reinterpret_cast<const __half2*>(&v1.w)); a6 += w1 * c.x; a7 += w1 * c.y;
    }
    for (; e < cnt; e += 4) {
        bool valid = (e + q) < cnt;
        int2 r = valid ? __ldg(&es[beg + e + q]) : make_int2(0, 0);  // w bits 0 -> 0.0f
        int4 v = __ldg(&fp[r.x + sub]);
        float w = __int_as_float(r.y);
        float2 c;
        c = __half22float2(*reinterpret_cast<const __half2*>(&v.x)); a0 += w * c.x; a1 += w * c.y;
        c = __half22float2(*reinterpret_cast<const __half2*>(&v.y)); a2 += w * c.x; a3 += w * c.y;
        c = __half22float2(*reinterpret_cast<const __half2*>(&v.z)); a4 += w * c.x; a5 += w * c.y;
        c = __half22float2(*reinterpret_cast<const __half2*>(&v.w)); a6 += w * c.x; a7 += w * c.y;
    }

    // fold quarter partials (sum over q for each slot position)
    #pragma unroll
    for (int o = 8; o <= 16; o <<= 1) {
        a0 += __shfl_xor_sync(0xffffffffu, a0, o);
        a1 += __shfl_xor_sync(0xffffffffu, a1, o);
        a2 += __shfl_xor_sync(0xffffffffu, a2, o);
        a3 += __shfl_xor_sync(0xffffffffu, a3, o);
        a4 += __shfl_xor_sync(0xffffffffu, a4, o);
        a5 += __shfl_xor_sync(0xffffffffu, a5, o);
        a6 += __shfl_xor_sync(0xffffffffu, a6, o);
        a7 += __shfl_xor_sync(0xffffffffu, a7, o);
    }

    if (q != 0) return;

    float din = g_dis[node];
    int ridx = node * S16 + sub;
    int4 pv = __ldg(&fp[ridx]);          // prev = f[STEP-1] row
    float2 p0 = __half22float2(*reinterpret_cast<const __half2*>(&pv.x));
    float2 p1 = __half22float2(*reinterpret_cast<const __half2*>(&pv.y));
    float2 p2 = __half22float2(*reinterpret_cast<const __half2*>(&pv.z));
    float2 p3 = __half22float2(*reinterpret_cast<const __half2*>(&pv.w));
    float o0 = p0.x - din * a0, o1 = p0.y - din * a1;
    float o2 = p1.x - din * a2, o3 = p1.y - din * a3;
    float o4 = p2.x - din * a4, o5 = p2.y - din * a5;
    float o6 = p3.x - din * a6, o7 = p3.y - din * a7;

    if (!FINAL) {
        int4* __restrict__ fn =
            (STEP == 1) ? (int4*)g_f16_1 :
            (STEP == 2) ? (int4*)g_f16_2 :
                          (int4*)g_f16_3;
        __half2 s0 = __floats2half2_rn(o0, o1);
        __half2 s1 = __floats2half2_rn(o2, o3);
        __half2 s2 = __floats2half2_rn(o4, o5);
        __half2 s3 = __floats2half2_rn(o6, o7);
        int4 st;
        st.x = *reinterpret_cast<const int*>(&s0);
        st.y = *reinterpret_cast<const int*>(&s1);
        st.z = *reinterpret_cast<const int*>(&s2);
        st.w = *reinterpret_cast<const int*>(&s3);
        fn[ridx] = st;
    } else {
        // h = TH0*x + TH1*f1 + TH2*f2 + TH3*f3 + TH4*out   (prev row above IS f3)
        int4 v1 = __ldg(&((const int4*)g_f16_1)[ridx]);
        int4 v2 = __ldg(&((const int4*)g_f16_2)[ridx]);
        float4 x0 = __ldg(&((const float4*)x)[node * 16 + sub * 2]);
        float4 x1 = __ldg(&((const float4*)x)[node * 16 + sub * 2 + 1]);
        float2 f1a = __half22float2(*reinterpret_cast<const __half2*>(&v1.x));
        float2 f1b = __half22float2(*reinterpret_cast<const __half2*>(&v1.y));
        float2 f1c = __half22float2(*reinterpret_cast<const __half2*>(&v1.z));
        float2 f1d = __half22float2(*reinterpret_cast<const __half2*>(&v1.w));
        float2 f2a = __half22float2(*reinterpret_cast<const __half2*>(&v2.x));
        float2 f2b = __half22float2(*reinterpret_cast<const __half2*>(&v2.y));
        float2 f2c = __half22float2(*reinterpret_cast<const __half2*>(&v2.z));
        float2 f2d = __half22float2(*reinterpret_cast<const __half2*>(&v2.w));
        float4 h0, h1;
        h0.x = TH0 * x0.x + TH1 * f1a.x + TH2 * f2a.x + TH3 * p0.x + TH4 * o0;
        h0.y = TH0 * x0.y + TH1 * f1a.y + TH2 * f2a.y + TH3 * p0.y + TH4 * o1;
        h0.z = TH0 * x0.z + TH1 * f1b.x + TH2 * f2b.x + TH3 * p1.x + TH4 * o2;
        h0.w = TH0 * x0.w + TH1 * f1b.y + TH2 * f2b.y + TH3 * p1.y + TH4 * o3;
        h1.x = TH0 * x1.x + TH1 * f1c.x + TH2 * f2c.x + TH3 * p2.x + TH4 * o4;
        h1.y = TH0 * x1.y + TH1 * f1c.y + TH2 * f2c.y + TH3 * p2.y + TH4 * o5;
        h1.z = TH0 * x1.z + TH1 * f1d.x + TH2 * f2d.x + TH3 * p3.x + TH4 * o6;
        h1.w = TH0 * x1.w + TH1 * f1d.y + TH2 * f2d.y + TH3 * p3.y + TH4 * o7;
        ((float4*)hOut)[node * 16 + sub * 2] = h0;
        ((float4*)hOut)[node * 16 + sub * 2 + 1] = h1;
    }
}

// ---------------- launcher ----------------

extern "C" void kernel_launch(void* const* d_in, const int* in_sizes, int n_in,
                              void* d_out, int out_size)
{
    const float* x    = (const float*)d_in[0];   // [N, 64] fp32
    const int*   edge = (const int*)d_in[1];     // [2, E] int32

    const int n = NN;
    const int e4 = NE / 4;
    const int n2 = NN * F2;
    const int NB_SCAN = (n + 1023) / 1024;

    float* h = (float*)d_out;

    k_zero_tohalf<<<(n2 + 255) / 256, 256>>>(x, n, n2);
    k_hist<<<(e4 + 255) / 256, 256>>>(edge, e4);
    k_scan1<<<NB_SCAN, 1024>>>(n);
    k_scan2<<<1, 32>>>(NB_SCAN);
    k_scan3<<<NB_SCAN, 1024>>>(n);
    k_scatter<<<(e4 + 255) / 256, 256>>>(edge, e4);

    const int TPB = 256;
    const int NBLK = (n * 32 + TPB - 1) / TPB;   // warp per node

    k_step<1, false><<<NBLK, TPB>>>(x, h, n);
    k_step<2, false><<<NBLK, TPB>>>(x, h, n);
    k_step<3, false><<<NBLK, TPB>>>(x, h, n);
    k_step<4, true ><<<NBLK, TPB>>>(x, h, n);
}

// round 9
// speedup vs baseline: 1.2234x; 1.0339x over previous
#include <cuda_runtime.h>
#include <cuda_fp16.h>
#include <cstdint>

#define NN 100000
#define NE 1600000
#define FF 64
#define F2 (FF/2)   // float2 lanes per row
#define S16 8       // 16-byte slots per row (64 halves = 128B = 8 x 16B)

#define TH0 0.6f
#define TH1 (-0.4f)
#define TH2 0.3f
#define TH3 (-0.2f)
#define TH4 0.1f

// ---- scratch (static device globals; no runtime allocation) ----
__device__ __half g_f16_0[NN * FF];
__device__ __half g_f16_1[NN * FF];
__device__ __half g_f16_2[NN * FF];
__device__ __half g_f16_3[NN * FF];
__device__ int    g_deg[NN];
__device__ int    g_off[NN];
__device__ int    g_cursor[NN];
__device__ float  g_dis[NN];
__device__ int2   g_edgeSorted[NE];   // .x = src*8 (16B-slot row base), .y = bits(dis[src])
__device__ int    g_blockSums[256];

// ---------------- preprocessing ----------------

// zero deg AND convert x -> fp16 in one launch (grid over n2)
__global__ void k_zero_tohalf(const float* __restrict__ x, int n, int n2) {
    int i = blockIdx.x * blockDim.x + threadIdx.x;
    if (i < n2) {
        float2 v = ((const float2*)x)[i];
        ((__half2*)g_f16_0)[i] = __float22half2_rn(v);
    }
    if (i < n) g_deg[i] = 0;
}

__global__ void k_hist(const int* __restrict__ edge, int e4) {
    int i = blockIdx.x * blockDim.x + threadIdx.x;
    if (i < e4) {
        int4 d = ((const int4*)(edge + NE))[i];
        atomicAdd(&g_deg[d.x], 1);
        atomicAdd(&g_deg[d.y], 1);
        atomicAdd(&g_deg[d.z], 1);
        atomicAdd(&g_deg[d.w], 1);
    }
}

// scan phase 1, also computes g_dis from deg (deg already read here)
__global__ void k_scan1(int n) {
    __shared__ int warpSums[32];
    int i = blockIdx.x * 1024 + threadIdx.x;
    int v = (i < n) ? g_deg[i] : 0;
    if (i < n) g_dis[i] = rsqrtf((float)(v < 1 ? 1 : v));
    int lane = threadIdx.x & 31, wid = threadIdx.x >> 5;
    int x = v;
    #pragma unroll
    for (int o = 1; o < 32; o <<= 1) {
        int t = __shfl_up_sync(0xffffffffu, x, o);
        if (lane >= o) x += t;
    }
    if (lane == 31) warpSums[wid] = x;
    __syncthreads();
    if (wid == 0) {
        int s = warpSums[lane];
        #pragma unroll
        for (int o = 1; o < 32; o <<= 1) {
            int t = __shfl_up_sync(0xffffffffu, s, o);
            if (lane >= o) s += t;
        }
        warpSums[lane] = s;
    }
    __syncthreads();
    int prefix = (wid > 0 ? warpSums[wid - 1] : 0) + (x - v);
    if (i < n) g_off[i] = prefix;
    if (threadIdx.x == 1023) g_blockSums[blockIdx.x] = warpSums[31];
}

// parallel exclusive scan of up to 128 block sums (one 128-thread block)
__global__ void k_scan2(int nb) {
    __shared__ int warpTot[4];
    int t = threadIdx.x;             // 0..127
    int v = (t < nb) ? g_blockSums[t] : 0;
    int lane = t & 31, wid = t >> 5;
    int x = v;
    #pragma unroll
    for (int o = 1; o < 32; o <<= 1) {
        int s = __shfl_up_sync(0xffffffffu, x, o);
        if (lane >= o) x += s;
    }
    if (lane == 31) warpTot[wid] = x;
    __syncthreads();
    int base = 0;
    #pragma unroll
    for (int w = 0; w < 4; w++) base += (w < wid) ? warpTot[w] : 0;
    if (t < nb) g_blockSums[t] = base + x - v;   // exclusive
}

// add block offsets; also init cursor to the FINAL offset so scatter needs no g_off read
__global__ void k_scan3(int n) {
    int i = blockIdx.x * 1024 + threadIdx.x;
    if (i < n) {
        int o = g_off[i] + g_blockSums[blockIdx.x];
        g_off[i] = o;
        g_cursor[i] = o;
    }
}

__global__ void k_scatter(const int* __restrict__ edge, int e4) {
    int i = blockIdx.x * blockDim.x + threadIdx.x;
    if (i < e4) {
        int4 s = ((const int4*)edge)[i];
        int4 d = ((const int4*)(edge + NE))[i];
        float w0 = g_dis[s.x], w1 = g_dis[s.y], w2 = g_dis[s.z], w3 = g_dis[s.w];
        int p0 = atomicAdd(&g_cursor[d.x], 1);
        int p1 = atomicAdd(&g_cursor[d.y], 1);
        int p2 = atomicAdd(&g_cursor[d.z], 1);
        int p3 = atomicAdd(&g_cursor[d.w], 1);
        g_edgeSorted[p0] = make_int2(s.x * S16, __float_as_int(w0));
        g_edgeSorted[p1] = make_int2(s.y * S16, __float_as_int(w1));
        g_edgeSorted[p2] = make_int2(s.z * S16, __float_as_int(w2));
        g_edgeSorted[p3] = make_int2(s.w * S16, __float_as_int(w3));
    }
}

// ---------------- propagation step ----------------
// Warp per node. Each lane owns a 16B slice (8 halves) of the 128B row; the
// four quarter-warps process 4 edges per gather LDG.128 (512B/warp-instr).
// Edge records: one LDG.64 covers 4 records (quarters read distinct records).
// Quarter partials folded with shfl_xor(8) + shfl_xor(16).
// FINAL=true fuses the polynomial combine: writes h = th0*x + ... directly.

template <int STEP, bool FINAL>
__global__ void __launch_bounds__(256) k_step(const float* __restrict__ x,
                                              float* __restrict__ hOut, int n) {
    int node = (blockIdx.x * blockDim.x + threadIdx.x) >> 5;
    int lane = threadIdx.x & 31;
    if (node >= n) return;
    int q   = lane >> 3;     // quarter 0..3
    int sub = lane & 7;      // 16B slot within row

    const int4* __restrict__ fp =
        (STEP == 1) ? (const int4*)g_f16_0 :
        (STEP == 2) ? (const int4*)g_f16_1 :
        (STEP == 3) ? (const int4*)g_f16_2 :
                      (const int4*)g_f16_3;

    int beg = g_off[node];
    int cnt = g_deg[node];
    const int2* __restrict__ es = (const int2*)g_edgeSorted;

    float a0 = 0.f, a1 = 0.f, a2 = 0.f, a3 = 0.f;
    float a4 = 0.f, a5 = 0.f, a6 = 0.f, a7 = 0.f;

    int e = 0;
    for (; e + 7 < cnt; e += 8) {
        int2 r0 = __ldg(&es[beg + e + q]);
        int2 r1 = __ldg(&es[beg + e + 4 + q]);
        int4 v0 = __ldg(&fp[r0.x + sub]);
        int4 v1 = __ldg(&fp[r1.x + sub]);
        float w0 = __int_as_float(r0.y);
        float w1 = __int_as_float(r1.y);
        float2 c;
        c = __half22float2(*reinterpret_cast<const __half2*>(&v0.x)); a0 += w0 * c.x; a1 += w0 * c.y;
        c = __half22float2(*reinterpret_cast<const __half2*>(&v0.y)); a2 += w0 * c.x; a3 += w0 * c.y;
        c = __half22float2(*reinterpret_cast<const __half2*>(&v0.z)); a4 += w0 * c.x; a5 += w0 * c.y;
        c = __half22float2(*reinterpret_cast<const __half2*>(&v0.w)); a6 += w0 * c.x; a7 += w0 * c.y;
        c = __half22float2(*reinterpret_cast<const __half2*>(&v1.x)); a0 += w1 * c.x; a1 += w1 * c.y;
        c = __half22float2(*reinterpret_cast<const __half2*>(&v1.y)); a2 += w1 * c.x; a3 += w1 * c.y;
        c = __half22float2(*reinterpret_cast<const __half2*>(&v1.z)); a4 += w1 * c.x; a5 += w1 * c.y;
        c = __half22float2(*reinterpret_cast<const __half2*>(&v1.w)); a6 += w1 * c.x; a7 += w1 * c.y;
    }
    for (; e < cnt; e += 4) {
        bool valid = (e + q) < cnt;
        int2 r = valid ? __ldg(&es[beg + e + q]) : make_int2(0, 0);  // w bits 0 -> 0.0f
        int4 v = __ldg(&fp[r.x + sub]);
        float w = __int_as_float(r.y);
        float2 c;
        c = __half22float2(*reinterpret_cast<const __half2*>(&v.x)); a0 += w * c.x; a1 += w * c.y;
        c = __half22float2(*reinterpret_cast<const __half2*>(&v.y)); a2 += w * c.x; a3 += w * c.y;
        c = __half22float2(*reinterpret_cast<const __half2*>(&v.z)); a4 += w * c.x; a5 += w * c.y;
        c = __half22float2(*reinterpret_cast<const __half2*>(&v.w)); a6 += w * c.x; a7 += w * c.y;
    }

    // fold quarter partials (sum over q for each slot position)
    #pragma unroll
    for (int o = 8; o <= 16; o <<= 1) {
        a0 += __shfl_xor_sync(0xffffffffu, a0, o);
        a1 += __shfl_xor_sync(0xffffffffu, a1, o);
        a2 += __shfl_xor_sync(0xffffffffu, a2, o);
        a3 += __shfl_xor_sync(0xffffffffu, a3, o);
        a4 += __shfl_xor_sync(0xffffffffu, a4, o);
        a5 += __shfl_xor_sync(0xffffffffu, a5, o);
        a6 += __shfl_xor_sync(0xffffffffu, a6, o);
        a7 += __shfl_xor_sync(0xffffffffu, a7, o);
    }

    if (q != 0) return;

    float din = g_dis[node];
    int ridx = node * S16 + sub;
    int4 pv = __ldg(&fp[ridx]);          // prev = f[STEP-1] row
    float2 p0 = __half22float2(*reinterpret_cast<const __half2*>(&pv.x));
    float2 p1 = __half22float2(*reinterpret_cast<const __half2*>(&pv.y));
    float2 p2 = __half22float2(*reinterpret_cast<const __half2*>(&pv.z));
    float2 p3 = __half22float2(*reinterpret_cast<const __half2*>(&pv.w));
    float o0 = p0.x - din * a0, o1 = p0.y - din * a1;
    float o2 = p1.x - din * a2, o3 = p1.y - din * a3;
    float o4 = p2.x - din * a4, o5 = p2.y - din * a5;
    float o6 = p3.x - din * a6, o7 = p3.y - din * a7;

    if (!FINAL) {
        int4* __restrict__ fn =
            (STEP == 1) ? (int4*)g_f16_1 :
            (STEP == 2) ? (int4*)g_f16_2 :
                          (int4*)g_f16_3;
        __half2 s0 = __floats2half2_rn(o0, o1);
        __half2 s1 = __floats2half2_rn(o2, o3);
        __half2 s2 = __floats2half2_rn(o4, o5);
        __half2 s3 = __floats2half2_rn(o6, o7);
        int4 st;
        st.x = *reinterpret_cast<const int*>(&s0);
        st.y = *reinterpret_cast<const int*>(&s1);
        st.z = *reinterpret_cast<const int*>(&s2);
        st.w = *reinterpret_cast<const int*>(&s3);
        fn[ridx] = st;
    } else {
        // h = TH0*x + TH1*f1 + TH2*f2 + TH3*f3 + TH4*out   (prev row above IS f3)
        int4 v1 = __ldg(&((const int4*)g_f16_1)[ridx]);
        int4 v2 = __ldg(&((const int4*)g_f16_2)[ridx]);
        float4 x0 = __ldg(&((const float4*)x)[node * 16 + sub * 2]);
        float4 x1 = __ldg(&((const float4*)x)[node * 16 + sub * 2 + 1]);
        float2 f1a = __half22float2(*reinterpret_cast<const __half2*>(&v1.x));
        float2 f1b = __half22float2(*reinterpret_cast<const __half2*>(&v1.y));
        float2 f1c = __half22float2(*reinterpret_cast<const __half2*>(&v1.z));
        float2 f1d = __half22float2(*reinterpret_cast<const __half2*>(&v1.w));
        float2 f2a = __half22float2(*reinterpret_cast<const __half2*>(&v2.x));
        float2 f2b = __half22float2(*reinterpret_cast<const __half2*>(&v2.y));
        float2 f2c = __half22float2(*reinterpret_cast<const __half2*>(&v2.z));
        float2 f2d = __half22float2(*reinterpret_cast<const __half2*>(&v2.w));
        float4 h0, h1;
        h0.x = TH0 * x0.x + TH1 * f1a.x + TH2 * f2a.x + TH3 * p0.x + TH4 * o0;
        h0.y = TH0 * x0.y + TH1 * f1a.y + TH2 * f2a.y + TH3 * p0.y + TH4 * o1;
        h0.z = TH0 * x0.z + TH1 * f1b.x + TH2 * f2b.x + TH3 * p1.x + TH4 * o2;
        h0.w = TH0 * x0.w + TH1 * f1b.y + TH2 * f2b.y + TH3 * p1.y + TH4 * o3;
        h1.x = TH0 * x1.x + TH1 * f1c.x + TH2 * f2c.x + TH3 * p2.x + TH4 * o4;
        h1.y = TH0 * x1.y + TH1 * f1c.y + TH2 * f2c.y + TH3 * p2.y + TH4 * o5;
        h1.z = TH0 * x1.z + TH1 * f1d.x + TH2 * f2d.x + TH3 * p3.x + TH4 * o6;
        h1.w = TH0 * x1.w + TH1 * f1d.y + TH2 * f2d.y + TH3 * p3.y + TH4 * o7;
        ((float4*)hOut)[node * 16 + sub * 2] = h0;
        ((float4*)hOut)[node * 16 + sub * 2 + 1] = h1;
    }
}

// ---------------- launcher ----------------

extern "C" void kernel_launch(void* const* d_in, const int* in_sizes, int n_in,
                              void* d_out, int out_size)
{
    const float* x    = (const float*)d_in[0];   // [N, 64] fp32
    const int*   edge = (const int*)d_in[1];     // [2, E] int32

    const int n = NN;
    const int e4 = NE / 4;
    const int n2 = NN * F2;
    const int NB_SCAN = (n + 1023) / 1024;   // 98 <= 128

    float* h = (float*)d_out;

    k_zero_tohalf<<<(n2 + 255) / 256, 256>>>(x, n, n2);
    k_hist<<<(e4 + 255) / 256, 256>>>(edge, e4);
    k_scan1<<<NB_SCAN, 1024>>>(n);
    k_scan2<<<1, 128>>>(NB_SCAN);
    k_scan3<<<NB_SCAN, 1024>>>(n);
    k_scatter<<<(e4 + 255) / 256, 256>>>(edge, e4);

    const int TPB = 256;
    const int NBLK = (n * 32 + TPB - 1) / TPB;   // warp per node

    k_step<1, false><<<NBLK, TPB>>>(x, h, n);
    k_step<2, false><<<NBLK, TPB>>>(x, h, n);
    k_step<3, false><<<NBLK, TPB>>>(x, h, n);
    k_step<4, true ><<<NBLK, TPB>>>(x, h, n);
}

// round 13
// speedup vs baseline: 1.2236x; 1.0002x over previous
#include <cuda_runtime.h>
#include <cuda_fp16.h>
#include <cstdint>

#define NN 100000
#define NE 1600000
#define FF 64
#define F2 (FF/2)   // float2 lanes per row
#define S16 8       // 16-byte slots per row (64 halves = 128B = 8 x 16B)

#define TH0 0.6f
#define TH1 (-0.4f)
#define TH2 0.3f
#define TH3 (-0.2f)
#define TH4 0.1f

// ---- scratch (static device globals; no runtime allocation) ----
__device__ __half g_f16_0[NN * FF];
__device__ __half g_f16_1[NN * FF];
__device__ __half g_f16_2[NN * FF];
__device__ __half g_f16_3[NN * FF];
__device__ int    g_deg[NN];
__device__ int    g_off[NN];
__device__ int    g_cursor[NN];
__device__ float  g_dis[NN];
__device__ int2   g_edgeSorted[NE];   // .x = src*8 (16B-slot row base), .y = bits(dis[src])
__device__ int    g_blockSums[256];

// ---------------- preprocessing ----------------

// zero deg AND convert x -> fp16 in one launch (grid over n2)
__global__ void k_zero_tohalf(const float* __restrict__ x, int n, int n2) {
    int i = blockIdx.x * blockDim.x + threadIdx.x;
    if (i < n2) {
        float2 v = ((const float2*)x)[i];
        ((__half2*)g_f16_0)[i] = __float22half2_rn(v);
    }
    if (i < n) g_deg[i] = 0;
}

__global__ void k_hist(const int* __restrict__ edge, int e4) {
    int i = blockIdx.x * blockDim.x + threadIdx.x;
    if (i < e4) {
        int4 d = ((const int4*)(edge + NE))[i];
        atomicAdd(&g_deg[d.x], 1);
        atomicAdd(&g_deg[d.y], 1);
        atomicAdd(&g_deg[d.z], 1);
        atomicAdd(&g_deg[d.w], 1);
    }
}

// scan phase 1, also computes g_dis from deg (deg already read here)
__global__ void k_scan1(int n) {
    __shared__ int warpSums[32];
    int i = blockIdx.x * 1024 + threadIdx.x;
    int v = (i < n) ? g_deg[i] : 0;
    if (i < n) g_dis[i] = rsqrtf((float)(v < 1 ? 1 : v));
    int lane = threadIdx.x & 31, wid = threadIdx.x >> 5;
    int x = v;
    #pragma unroll
    for (int o = 1; o < 32; o <<= 1) {
        int t = __shfl_up_sync(0xffffffffu, x, o);
        if (lane >= o) x += t;
    }
    if (lane == 31) warpSums[wid] = x;
    __syncthreads();
    if (wid == 0) {
        int s = warpSums[lane];
        #pragma unroll
        for (int o = 1; o < 32; o <<= 1) {
            int t = __shfl_up_sync(0xffffffffu, s, o);
            if (lane >= o) s += t;
        }
        warpSums[lane] = s;
    }
    __syncthreads();
    int prefix = (wid > 0 ? warpSums[wid - 1] : 0) + (x - v);
    if (i < n) g_off[i] = prefix;
    if (threadIdx.x == 1023) g_blockSums[blockIdx.x] = warpSums[31];
}

// add block offsets (each block redundantly reduces preceding blockSums —
// replaces the separate single-block scan2 kernel); also init cursor to the
// FINAL offset so scatter needs no g_off read
__global__ void k_scan3(int n) {
    __shared__ int sBase;
    int b = blockIdx.x;
    if (threadIdx.x < 32) {
        int lane = threadIdx.x;
        int acc = 0;
        for (int j = lane; j < b; j += 32) acc += g_blockSums[j];  // b <= 98 -> <=4 iters
        #pragma unroll
        for (int o = 16; o; o >>= 1) acc += __shfl_xor_sync(0xffffffffu, acc, o);
        if (lane == 0) sBase = acc;
    }
    __syncthreads();
    int i = b * 1024 + threadIdx.x;
    if (i < n) {
        int o = g_off[i] + sBase;
        g_off[i] = o;
        g_cursor[i] = o;
    }
}

__global__ void k_scatter(const int* __restrict__ edge, int e4) {
    int i = blockIdx.x * blockDim.x + threadIdx.x;
    if (i < e4) {
        int4 s = ((const int4*)edge)[i];
        int4 d = ((const int4*)(edge + NE))[i];
        float w0 = g_dis[s.x], w1 = g_dis[s.y], w2 = g_dis[s.z], w3 = g_dis[s.w];
        int p0 = atomicAdd(&g_cursor[d.x], 1);
        int p1 = atomicAdd(&g_cursor[d.y], 1);
        int p2 = atomicAdd(&g_cursor[d.z], 1);
        int p3 = atomicAdd(&g_cursor[d.w], 1);
        g_edgeSorted[p0] = make_int2(s.x * S16, __float_as_int(w0));
        g_edgeSorted[p1] = make_int2(s.y * S16, __float_as_int(w1));
        g_edgeSorted[p2] = make_int2(s.z * S16, __float_as_int(w2));
        g_edgeSorted[p3] = make_int2(s.w * S16, __float_as_int(w3));
    }
}

// ---------------- propagation step ----------------
// Warp per node. Each lane owns a 16B slice (8 halves) of the 128B row; the
// four quarter-warps process 4 edges per gather LDG.128 (512B/warp-instr).
// Edge records: one LDG.64 covers 4 records (quarters read distinct records).
// Quarter partials folded with shfl_xor(8) + shfl_xor(16).
// FINAL=true fuses the polynomial combine: writes h = th0*x + ... directly.

template <int STEP, bool FINAL>
__global__ void __launch_bounds__(256) k_step(const float* __restrict__ x,
                                              float* __restrict__ hOut, int n) {
    int node = (blockIdx.x * blockDim.x + threadIdx.x) >> 5;
    int lane = threadIdx.x & 31;
    if (node >= n) return;
    int q   = lane >> 3;     // quarter 0..3
    int sub = lane & 7;      // 16B slot within row

    const int4* __restrict__ fp =
        (STEP == 1) ? (const int4*)g_f16_0 :
        (STEP == 2) ? (const int4*)g_f16_1 :
        (STEP == 3) ? (const int4*)g_f16_2 :
                      (const int4*)g_f16_3;

    int beg = g_off[node];
    int cnt = g_deg[node];
    const int2* __restrict__ es = (const int2*)g_edgeSorted;

    float a0 = 0.f, a1 = 0.f, a2 = 0.f, a3 = 0.f;
    float a4 = 0.f, a5 = 0.f, a6 = 0.f, a7 = 0.f;

    int e = 0;
    for (; e + 7 < cnt; e += 8) {
        int2 r0 = __ldg(&es[beg + e + q]);
        int2 r1 = __ldg(&es[beg + e + 4 + q]);
        int4 v0 = __ldg(&fp[r0.x + sub]);
        int4 v1 = __ldg(&fp[r1.x + sub]);
        float w0 = __int_as_float(r0.y);
        float w1 = __int_as_float(r1.y);
        float2 c;
        c = __half22float2(*reinterpret_cast<const __half2*>(&v0.x)); a0 += w0 * c.x; a1 += w0 * c.y;
        c = __half22float2(*reinterpret_cast<const __half2*>(&v0.y)); a2 += w0 * c.x; a3 += w0 * c.y;
        c = __half22float2(*reinterpret_cast<const __half2*>(&v0.z)); a4 += w0 * c.x; a5 += w0 * c.y;
        c = __half22float2(*reinterpret_cast<const __half2*>(&v0.w)); a6 += w0 * c.x; a7 += w0 * c.y;
        c = __half22float2(*reinterpret_cast<const __half2*>(&v1.x)); a0 += w1 * c.x; a1 += w1 * c.y;
        c = __half22float2(*reinterpret_cast<const __half2*>(&v1.y)); a2 += w1 * c.x; a3 += w1 * c.y;
        c = __half22float2(*reinterpret_cast<const __half2*>(&v1.z)); a4 += w1 * c.x; a5 += w1 * c.y;
        c = __half22float2(*reinterpret_cast<const __half2*>(&v1.w)); a6 += w1 * c.x; a7 += w1 * c.y;
    }
    for (; e < cnt; e += 4) {
        bool valid = (e + q) < cnt;
        int2 r = valid ? __ldg(&es[beg + e + q]) : make_int2(0, 0);  // w bits 0 -> 0.0f
        int4 v = __ldg(&fp[r.x + sub]);
        float w = __int_as_float(r.y);
        float2 c;
        c = __half22float2(*reinterpret_cast<const __half2*>(&v.x)); a0 += w * c.x; a1 += w * c.y;
        c = __half22float2(*reinterpret_cast<const __half2*>(&v.y)); a2 += w * c.x; a3 += w * c.y;
        c = __half22float2(*reinterpret_cast<const __half2*>(&v.z)); a4 += w * c.x; a5 += w * c.y;
        c = __half22float2(*reinterpret_cast<const __half2*>(&v.w)); a6 += w * c.x; a7 += w * c.y;
    }

    // fold quarter partials (sum over q for each slot position)
    #pragma unroll
    for (int o = 8; o <= 16; o <<= 1) {
        a0 += __shfl_xor_sync(0xffffffffu, a0, o);
        a1 += __shfl_xor_sync(0xffffffffu, a1, o);
        a2 += __shfl_xor_sync(0xffffffffu, a2, o);
        a3 += __shfl_xor_sync(0xffffffffu, a3, o);
        a4 += __shfl_xor_sync(0xffffffffu, a4, o);
        a5 += __shfl_xor_sync(0xffffffffu, a5, o);
        a6 += __shfl_xor_sync(0xffffffffu, a6, o);
        a7 += __shfl_xor_sync(0xffffffffu, a7, o);
    }

    if (q != 0) return;

    float din = g_dis[node];
    int ridx = node * S16 + sub;
    int4 pv = __ldg(&fp[ridx]);          // prev = f[STEP-1] row
    float2 p0 = __half22float2(*reinterpret_cast<const __half2*>(&pv.x));
    float2 p1 = __half22float2(*reinterpret_cast<const __half2*>(&pv.y));
    float2 p2 = __half22float2(*reinterpret_cast<const __half2*>(&pv.z));
    float2 p3 = __half22float2(*reinterpret_cast<const __half2*>(&pv.w));
    float o0 = p0.x - din * a0, o1 = p0.y - din * a1;
    float o2 = p1.x - din * a2, o3 = p1.y - din * a3;
    float o4 = p2.x - din * a4, o5 = p2.y - din * a5;
    float o6 = p3.x - din * a6, o7 = p3.y - din * a7;

    if (!FINAL) {
        int4* __restrict__ fn =
            (STEP == 1) ? (int4*)g_f16_1 :
            (STEP == 2) ? (int4*)g_f16_2 :
                          (int4*)g_f16_3;
        __half2 s0 = __floats2half2_rn(o0, o1);
        __half2 s1 = __floats2half2_rn(o2, o3);
        __half2 s2 = __floats2half2_rn(o4, o5);
        __half2 s3 = __floats2half2_rn(o6, o7);
        int4 st;
        st.x = *reinterpret_cast<const int*>(&s0);
        st.y = *reinterpret_cast<const int*>(&s1);
        st.z = *reinterpret_cast<const int*>(&s2);
        st.w = *reinterpret_cast<const int*>(&s3);
        fn[ridx] = st;
    } else {
        // h = TH0*x + TH1*f1 + TH2*f2 + TH3*f3 + TH4*out   (prev row above IS f3)
        int4 v1 = __ldg(&((const int4*)g_f16_1)[ridx]);
        int4 v2 = __ldg(&((const int4*)g_f16_2)[ridx]);
        float4 x0 = __ldg(&((const float4*)x)[node * 16 + sub * 2]);
        float4 x1 = __ldg(&((const float4*)x)[node * 16 + sub * 2 + 1]);
        float2 f1a = __half22float2(*reinterpret_cast<const __half2*>(&v1.x));
        float2 f1b = __half22float2(*reinterpret_cast<const __half2*>(&v1.y));
        float2 f1c = __half22float2(*reinterpret_cast<const __half2*>(&v1.z));
        float2 f1d = __half22float2(*reinterpret_cast<const __half2*>(&v1.w));
        float2 f2a = __half22float2(*reinterpret_cast<const __half2*>(&v2.x));
        float2 f2b = __half22float2(*reinterpret_cast<const __half2*>(&v2.y));
        float2 f2c = __half22float2(*reinterpret_cast<const __half2*>(&v2.z));
        float2 f2d = __half22float2(*reinterpret_cast<const __half2*>(&v2.w));
        float4 h0, h1;
        h0.x = TH0 * x0.x + TH1 * f1a.x + TH2 * f2a.x + TH3 * p0.x + TH4 * o0;
        h0.y = TH0 * x0.y + TH1 * f1a.y + TH2 * f2a.y + TH3 * p0.y + TH4 * o1;
        h0.z = TH0 * x0.z + TH1 * f1b.x + TH2 * f2b.x + TH3 * p1.x + TH4 * o2;
        h0.w = TH0 * x0.w + TH1 * f1b.y + TH2 * f2b.y + TH3 * p1.y + TH4 * o3;
        h1.x = TH0 * x1.x + TH1 * f1c.x + TH2 * f2c.x + TH3 * p2.x + TH4 * o4;
        h1.y = TH0 * x1.y + TH1 * f1c.y + TH2 * f2c.y + TH3 * p2.y + TH4 * o5;
        h1.z = TH0 * x1.z + TH1 * f1d.x + TH2 * f2d.x + TH3 * p3.x + TH4 * o6;
        h1.w = TH0 * x1.w + TH1 * f1d.y + TH2 * f2d.y + TH3 * p3.y + TH4 * o7;
        ((float4*)hOut)[node * 16 + sub * 2] = h0;
        ((float4*)hOut)[node * 16 + sub * 2 + 1] = h1;
    }
}

// ---------------- launcher ----------------

extern "C" void kernel_launch(void* const* d_in, const int* in_sizes, int n_in,
                              void* d_out, int out_size)
{
    const float* x    = (const float*)d_in[0];   // [N, 64] fp32
    const int*   edge = (const int*)d_in[1];     // [2, E] int32

    const int n = NN;
    const int e4 = NE / 4;
    const int n2 = NN * F2;
    const int NB_SCAN = (n + 1023) / 1024;   // 98 <= 128

    float* h = (float*)d_out;

    k_zero_tohalf<<<(n2 + 255) / 256, 256>>>(x, n, n2);
    k_hist<<<(e4 + 255) / 256, 256>>>(edge, e4);
    k_scan1<<<NB_SCAN, 1024>>>(n);
    k_scan3<<<NB_SCAN, 1024>>>(n);
    k_scatter<<<(e4 + 255) / 256, 256>>>(edge, e4);

    const int TPB = 256;
    const int NBLK = (n * 32 + TPB - 1) / TPB;   // warp per node

    k_step<1, false><<<NBLK, TPB>>>(x, h, n);
    k_step<2, false><<<NBLK, TPB>>>(x, h, n);
    k_step<3, false><<<NBLK, TPB>>>(x, h, n);
    k_step<4, true ><<<NBLK, TPB>>>(x, h, n);
}